// round 15
// baseline (speedup 1.0000x reference)
#include <cuda_runtime.h>
#include <cuda_bf16.h>
#include <cstdint>
#include <math.h>

#define Nn 64
#define Cdim 128
#define Pdim 4096
#define Kdim 64

// ---- device scratch ----
__device__ float g_asum_p[Nn * 32 * Kdim];             // 512 KB (per-tile asum partials)
__device__ float g_vpart[(size_t)Nn * Cdim * Kdim];    // 2 MB   [n][c][k] red-accumulated
__device__ int   g_cnt[Nn];                            // tile-completion counters (self-resetting)

// ---- mma / ldmatrix wrappers ----
__device__ __forceinline__ uint32_t smem_u32(const void* p) {
    uint32_t a;
    asm("{ .reg .u64 t; cvta.to.shared.u64 t, %1; cvt.u32.u64 %0, t; }" : "=r"(a) : "l"(p));
    return a;
}
__device__ __forceinline__ void ldsm_x4(uint32_t* r, uint32_t addr) {
    asm volatile("ldmatrix.sync.aligned.m8n8.x4.shared.b16 {%0,%1,%2,%3}, [%4];"
                 : "=r"(r[0]), "=r"(r[1]), "=r"(r[2]), "=r"(r[3]) : "r"(addr));
}
__device__ __forceinline__ void ldsm_x2_trans(uint32_t* r, uint32_t addr) {
    asm volatile("ldmatrix.sync.aligned.m8n8.x2.trans.shared.b16 {%0,%1}, [%2];"
                 : "=r"(r[0]), "=r"(r[1]) : "r"(addr));
}
__device__ __forceinline__ void mma_bf16(float* d, const uint32_t* a, const uint32_t* b) {
    asm volatile(
        "mma.sync.aligned.m16n8k16.row.col.f32.bf16.bf16.f32 "
        "{%0,%1,%2,%3}, {%4,%5,%6,%7}, {%8,%9}, {%0,%1,%2,%3};"
        : "+f"(d[0]), "+f"(d[1]), "+f"(d[2]), "+f"(d[3])
        : "r"(a[0]), "r"(a[1]), "r"(a[2]), "r"(a[3]), "r"(b[0]), "r"(b[1]));
}
__device__ __forceinline__ void split_bf16(float v, __nv_bfloat16& h, __nv_bfloat16& l) {
    h = __float2bfloat16(v);
    l = __float2bfloat16(v - __bfloat162float(h));
}
__device__ __forceinline__ uint32_t cvt2bf(float lo, float hi) {
    uint32_t r;
    asm("cvt.rn.bf16x2.f32 %0, %1, %2;" : "=r"(r) : "f"(hi), "f"(lo));
    return r;
}
__device__ __forceinline__ float bfp_lo(uint32_t pair) { return __uint_as_float(pair << 16); }
__device__ __forceinline__ float bfp_hi(uint32_t pair) { return __uint_as_float(pair & 0xFFFF0000u); }
#define REDG_ADD(addr, v) \
    asm volatile("red.global.add.f32 [%0], %1;" :: "l"(addr), "f"(v) : "memory")

// =====================================================================
// K_zero: zero the vlad accumulator (2 MB) each launch.
// =====================================================================
__global__ __launch_bounds__(256) void k_zero() {
    int i = blockIdx.x * 256 + threadIdx.x;
    ((float4*)g_vpart)[i] = make_float4(0.f, 0.f, 0.f, 0.f);
}

// =====================================================================
// K_fused: per (n, 128-pixel tile): logits GEMM -> softmax -> vlad MMA
// partial -> REDG. Last tile-CTA per n performs the full finalization.
// smem 91648 B, 2 CTAs/SM.
// =====================================================================
#define OFF_WH 0                    // 64*136*2 = 17408
#define OFF_WL 17408
#define OFF_XF 34816                // x hi full: 128*136*2 = 34816
#define OFF_XL 69632                // x lo double buffer (a' staging later)
#define OFF_SP 87040                // s_part 1024 floats
#define OFF_SA 91136                // 64 floats
#define OFF_SB 91392                // 64 floats
#define L_SMEM 91648
#define XLPLANE 4352                // 32*136 elems per lo plane
// finalize-phase aliases (all regions dead by then)
#define F_VL 0                      // 64*129 floats = 33024 B (in WH+WL region)
#define F_AS 34816                  // 64 floats
#define F_RN 35328                  // 64 floats
#define F_RB 35840                  // 8 floats
#define F_GS 35904                  // 1 float
#define F_FLAG 35968                // 1 int

__global__ __launch_bounds__(256, 2) void k_fused(const float* __restrict__ x,
                                                  const float* __restrict__ conv_w,
                                                  const float* __restrict__ conv_b,
                                                  const float* __restrict__ cent,
                                                  float* __restrict__ out) {
    extern __shared__ __align__(16) char dsm[];
    __nv_bfloat16* wh = (__nv_bfloat16*)(dsm + OFF_WH);
    __nv_bfloat16* wl = (__nv_bfloat16*)(dsm + OFF_WL);
    __nv_bfloat16* xf = (__nv_bfloat16*)(dsm + OFF_XF);
    __nv_bfloat16* xlb = (__nv_bfloat16*)(dsm + OFF_XL);
    __nv_bfloat16* a_s = (__nv_bfloat16*)(dsm + OFF_XL);
    float* s_part = (float*)(dsm + OFF_SP);
    float* s_asum = (float*)(dsm + OFF_SA);
    float* s_b = (float*)(dsm + OFF_SB);

    const int n = blockIdx.y;
    const int p0 = blockIdx.x * 128;
    const int tid = threadIdx.x;
    const int w = tid >> 5, lane = tid & 31;
    const int pw = w * 16;

    const uint32_t u_wh = smem_u32(wh), u_wl = smem_u32(wl);
    const uint32_t u_xf = smem_u32(xf);

    // stage W hi/lo (64x128, pitch 136)
#pragma unroll
    for (int r = 0; r < 8; ++r) {
        int f4 = tid + r * 256;
        int row = f4 >> 5, col4 = f4 & 31;
        float4 v = *(const float4*)(conv_w + row * 128 + col4 * 4);
        __nv_bfloat16 h, l;
        split_bf16(v.x, h, l); wh[row * 136 + col4 * 4 + 0] = h; wl[row * 136 + col4 * 4 + 0] = l;
        split_bf16(v.y, h, l); wh[row * 136 + col4 * 4 + 1] = h; wl[row * 136 + col4 * 4 + 1] = l;
        split_bf16(v.z, h, l); wh[row * 136 + col4 * 4 + 2] = h; wl[row * 136 + col4 * 4 + 2] = l;
        split_bf16(v.w, h, l); wh[row * 136 + col4 * 4 + 3] = h; wl[row * 136 + col4 * 4 + 3] = l;
    }
    if (tid < 64) { s_b[tid] = conv_b[tid]; s_asum[tid] = 0.f; }

    float acc[4][2][4];
#pragma unroll
    for (int a = 0; a < 4; ++a)
#pragma unroll
        for (int b = 0; b < 2; ++b)
#pragma unroll
            for (int c = 0; c < 4; ++c) acc[a][b][c] = 0.f;

    const float* xg = x + (size_t)n * Cdim * Pdim + p0;
    const int rbase = tid >> 5;
    const int col4 = tid & 31;

    float ss0 = 0.f, ss1 = 0.f, ss2 = 0.f, ss3 = 0.f;
    float4 vx[4];

#pragma unroll
    for (int r = 0; r < 4; ++r)
        vx[r] = *(const float4*)(xg + (size_t)(rbase + 8 * r) * Pdim + col4 * 4);
    {
        __nv_bfloat16* cxl = xlb;
#pragma unroll
        for (int r = 0; r < 4; ++r) {
            float4 v = vx[r];
            ss0 += v.x * v.x; ss1 += v.y * v.y; ss2 += v.z * v.z; ss3 += v.w * v.w;
            uint32_t h01 = cvt2bf(v.x, v.y), h23 = cvt2bf(v.z, v.w);
            float l0 = v.x - bfp_lo(h01), l1 = v.y - bfp_hi(h01);
            float l2 = v.z - bfp_lo(h23), l3 = v.w - bfp_hi(h23);
            int row = rbase + 8 * r;
            *(uint2*)&xf[row * 136 + col4 * 4] = make_uint2(h01, h23);
            *(uint2*)&cxl[row * 136 + col4 * 4] = make_uint2(cvt2bf(l0, l1), cvt2bf(l2, l3));
        }
    }
    __syncthreads();

#pragma unroll
    for (int cbi = 0; cbi < 4; ++cbi) {
        const int cb = cbi * 32;
        if (cbi < 3) {
#pragma unroll
            for (int r = 0; r < 4; ++r)
                vx[r] = *(const float4*)(xg + (size_t)(cb + 32 + rbase + 8 * r) * Pdim + col4 * 4);
        }

        const uint32_t u_xl = smem_u32(xlb + (cbi & 1) * XLPLANE);
#pragma unroll
        for (int ks = 0; ks < 2; ++ks) {
            uint32_t bh[2][2], bl[2][2];
#pragma unroll
            for (int nt = 0; nt < 2; ++nt) {
                uint32_t offh = (uint32_t)(((cb + ks * 16 + (lane & 15)) * 136 + pw + nt * 8) * 2);
                uint32_t offl = (uint32_t)(((ks * 16 + (lane & 15)) * 136 + pw + nt * 8) * 2);
                ldsm_x2_trans(bh[nt], u_xf + offh);
                ldsm_x2_trans(bl[nt], u_xl + offl);
            }
#pragma unroll
            for (int mt = 0; mt < 4; ++mt) {
                uint32_t ah[4], al[4];
                uint32_t off = (uint32_t)(((mt * 16 + (lane & 15)) * 136 + cb + ks * 16 + (lane >> 4) * 8) * 2);
                ldsm_x4(ah, u_wh + off);
                ldsm_x4(al, u_wl + off);
#pragma unroll
                for (int nt = 0; nt < 2; ++nt) {
                    mma_bf16(acc[mt][nt], ah, bh[nt]);
                    mma_bf16(acc[mt][nt], ah, bl[nt]);
                    mma_bf16(acc[mt][nt], al, bh[nt]);
                }
            }
        }

        if (cbi < 3) {
            __nv_bfloat16* cxl = xlb + ((cbi + 1) & 1) * XLPLANE;
#pragma unroll
            for (int r = 0; r < 4; ++r) {
                float4 v = vx[r];
                ss0 += v.x * v.x; ss1 += v.y * v.y; ss2 += v.z * v.z; ss3 += v.w * v.w;
                uint32_t h01 = cvt2bf(v.x, v.y), h23 = cvt2bf(v.z, v.w);
                float l0 = v.x - bfp_lo(h01), l1 = v.y - bfp_hi(h01);
                float l2 = v.z - bfp_lo(h23), l3 = v.w - bfp_hi(h23);
                int row = rbase + 8 * r;
                *(uint2*)&xf[(cb + 32 + row) * 136 + col4 * 4] = make_uint2(h01, h23);
                *(uint2*)&cxl[row * 136 + col4 * 4] = make_uint2(cvt2bf(l0, l1), cvt2bf(l2, l3));
            }
        }
        __syncthreads();
    }

    // sumsq reduce (in place)
    *(float4*)&s_part[rbase * 128 + col4 * 4] = make_float4(ss0, ss1, ss2, ss3);
    __syncthreads();
    float tot = 0.f;
    if (tid < 128) {
#pragma unroll
        for (int q = 0; q < 8; ++q) tot += s_part[q * 128 + tid];
    }
    __syncthreads();
    if (tid < 128) s_part[tid] = 1.f / fmaxf(sqrtf(tot), 1e-12f);
    __syncthreads();
    float* s_inv = s_part;

    float iv0[2], iv1[2];
#pragma unroll
    for (int nt = 0; nt < 2; ++nt) {
        int c0 = pw + nt * 8 + (lane & 3) * 2;
        iv0[nt] = s_inv[c0];
        iv1[nt] = s_inv[c0 + 1];
    }
    float bb0[4], bb1[4];
#pragma unroll
    for (int mt = 0; mt < 4; ++mt) {
        bb0[mt] = s_b[mt * 16 + (lane >> 2)];
        bb1[mt] = s_b[mt * 16 + (lane >> 2) + 8];
    }
    float l[4][2][4];
#pragma unroll
    for (int mt = 0; mt < 4; ++mt)
#pragma unroll
        for (int nt = 0; nt < 2; ++nt) {
            l[mt][nt][0] = acc[mt][nt][0] * iv0[nt] + bb0[mt];
            l[mt][nt][1] = acc[mt][nt][1] * iv1[nt] + bb0[mt];
            l[mt][nt][2] = acc[mt][nt][2] * iv0[nt] + bb1[mt];
            l[mt][nt][3] = acc[mt][nt][3] * iv1[nt] + bb1[mt];
        }
    float mx0[2], mx1[2];
#pragma unroll
    for (int nt = 0; nt < 2; ++nt) {
        float m0 = -1e30f, m1 = -1e30f;
#pragma unroll
        for (int mt = 0; mt < 4; ++mt) {
            m0 = fmaxf(m0, fmaxf(l[mt][nt][0], l[mt][nt][2]));
            m1 = fmaxf(m1, fmaxf(l[mt][nt][1], l[mt][nt][3]));
        }
#pragma unroll
        for (int s = 4; s < 32; s <<= 1) {
            m0 = fmaxf(m0, __shfl_xor_sync(0xffffffffu, m0, s));
            m1 = fmaxf(m1, __shfl_xor_sync(0xffffffffu, m1, s));
        }
        mx0[nt] = m0; mx1[nt] = m1;
    }
    float sm0[2], sm1[2];
#pragma unroll
    for (int nt = 0; nt < 2; ++nt) {
        float s0 = 0.f, s1 = 0.f;
#pragma unroll
        for (int mt = 0; mt < 4; ++mt) {
            l[mt][nt][0] = __expf(l[mt][nt][0] - mx0[nt]); s0 += l[mt][nt][0];
            l[mt][nt][2] = __expf(l[mt][nt][2] - mx0[nt]); s0 += l[mt][nt][2];
            l[mt][nt][1] = __expf(l[mt][nt][1] - mx1[nt]); s1 += l[mt][nt][1];
            l[mt][nt][3] = __expf(l[mt][nt][3] - mx1[nt]); s1 += l[mt][nt][3];
        }
#pragma unroll
        for (int s = 4; s < 32; s <<= 1) {
            s0 += __shfl_xor_sync(0xffffffffu, s0, s);
            s1 += __shfl_xor_sync(0xffffffffu, s1, s);
        }
        sm0[nt] = 1.f / s0; sm1[nt] = 1.f / s1;
    }
    float srow0[4] = {0, 0, 0, 0}, srow1[4] = {0, 0, 0, 0};
#pragma unroll
    for (int mt = 0; mt < 4; ++mt) {
        int r0 = mt * 16 + (lane >> 2);
#pragma unroll
        for (int nt = 0; nt < 2; ++nt) {
            int c0 = pw + nt * 8 + (lane & 3) * 2;
            float a0 = l[mt][nt][0] * sm0[nt];
            float a1 = l[mt][nt][1] * sm1[nt];
            float a2 = l[mt][nt][2] * sm0[nt];
            float a3 = l[mt][nt][3] * sm1[nt];
            srow0[mt] += a0 + a1;
            srow1[mt] += a2 + a3;
            *(uint32_t*)&a_s[r0 * 136 + c0] = cvt2bf(a0 * iv0[nt], a1 * iv1[nt]);
            *(uint32_t*)&a_s[(r0 + 8) * 136 + c0] = cvt2bf(a2 * iv0[nt], a3 * iv1[nt]);
        }
    }
#pragma unroll
    for (int mt = 0; mt < 4; ++mt) {
        float t0 = srow0[mt], t1 = srow1[mt];
        t0 += __shfl_xor_sync(0xffffffffu, t0, 1); t0 += __shfl_xor_sync(0xffffffffu, t0, 2);
        t1 += __shfl_xor_sync(0xffffffffu, t1, 1); t1 += __shfl_xor_sync(0xffffffffu, t1, 2);
        if ((lane & 3) == 0) {
            atomicAdd(&s_asum[mt * 16 + (lane >> 2)], t0);
            atomicAdd(&s_asum[mt * 16 + (lane >> 2) + 8], t1);
        }
    }
    __syncthreads();
    if (tid < 64) g_asum_p[(n * 32 + blockIdx.x) * Kdim + tid] = s_asum[tid];

    // ---- vlad MMA: D[c=128][k=64] partial = xf[c,p] * a_s[k,p], K=128 px ----
    const uint32_t u_as = smem_u32(a_s);
    float acc2[8][4];
#pragma unroll
    for (int a = 0; a < 8; ++a)
#pragma unroll
        for (int b = 0; b < 4; ++b) acc2[a][b] = 0.f;

#pragma unroll
    for (int ks = 0; ks < 8; ++ks) {
        uint32_t ah[4];
        uint32_t offA = (uint32_t)(((w * 16 + (lane & 15)) * 136 + ks * 16 + (lane >> 4) * 8) * 2);
        ldsm_x4(ah, u_xf + offA);
#pragma unroll
        for (int ntp = 0; ntp < 4; ++ntp) {
            uint32_t b4[4];
            int row = ntp * 16 + ((lane >> 4) << 3) + (lane & 7);
            int col = ks * 16 + ((lane >> 3) & 1) * 8;
            ldsm_x4(b4, u_as + (uint32_t)((row * 136 + col) * 2));
            mma_bf16(acc2[2 * ntp], ah, b4);
            mma_bf16(acc2[2 * ntp + 1], ah, b4 + 2);
        }
    }

    // red-accumulate partial into g_vpart[n][c][k]
    float* vp = g_vpart + (size_t)n * (Cdim * Kdim);
    {
        int r0v = w * 16 + (lane >> 2);
        int c0v = (lane & 3) * 2;
#pragma unroll
        for (int nt = 0; nt < 8; ++nt) {
            float* d0 = vp + (size_t)r0v * Kdim + nt * 8 + c0v;
            float* d1 = vp + (size_t)(r0v + 8) * Kdim + nt * 8 + c0v;
            REDG_ADD(d0, acc2[nt][0]);
            REDG_ADD(d0 + 1, acc2[nt][1]);
            REDG_ADD(d1, acc2[nt][2]);
            REDG_ADD(d1 + 1, acc2[nt][3]);
        }
    }

    // ---- last-CTA-done finalization (threadFenceReduction pattern) ----
    __threadfence();
    __syncthreads();
    int* s_flag = (int*)(dsm + F_FLAG);
    if (tid == 0) {
        int old = atomicAdd(&g_cnt[n], 1);
        *s_flag = (old == 31);
    }
    __syncthreads();
    if (!*s_flag) return;

    // This CTA is the 32nd for image n: all REDGs + asum partials are visible.
    float* vl = (float*)(dsm + F_VL);           // [64][129]
    float* f_as = (float*)(dsm + F_AS);
    float* f_rn = (float*)(dsm + F_RN);
    float* f_rb = (float*)(dsm + F_RB);
    float* f_gs = (float*)(dsm + F_GS);

    if (tid == 0) g_cnt[n] = 0;                 // reset for next launch/replay
    if (tid < 64) {
        float s = 0.f;
#pragma unroll
        for (int t = 0; t < 32; ++t) s += g_asum_p[(n * 32 + t) * Kdim + tid];
        f_as[tid] = s;
    }
    __syncthreads();

#pragma unroll
    for (int it = 0; it < 8; ++it) {
        int idx = (tid + it * 256) * 4;
        float4 s = *(const float4*)(vp + idx);
        int c = idx >> 6, k = idx & 63;
        vl[(k + 0) * 129 + c] = s.x - f_as[k + 0] * cent[(k + 0) * Cdim + c];
        vl[(k + 1) * 129 + c] = s.y - f_as[k + 1] * cent[(k + 1) * Cdim + c];
        vl[(k + 2) * 129 + c] = s.z - f_as[k + 2] * cent[(k + 2) * Cdim + c];
        vl[(k + 3) * 129 + c] = s.w - f_as[k + 3] * cent[(k + 3) * Cdim + c];
    }
    __syncthreads();

#pragma unroll
    for (int kk = 0; kk < 8; ++kk) {
        int k = w * 8 + kk;
        float t = 0.f;
#pragma unroll
        for (int m = 0; m < 4; ++m) {
            float v = vl[k * 129 + lane + m * 32];
            t += v * v;
        }
#pragma unroll
        for (int off = 16; off > 0; off >>= 1) t += __shfl_xor_sync(0xffffffffu, t, off);
        if (lane == 0) f_rn[k] = 1.f / fmaxf(sqrtf(t), 1e-12f);
    }
    __syncthreads();

    float gtot = 0.f;
#pragma unroll
    for (int it = 0; it < 32; ++it) {
        int idx = tid + it * 256;
        int k = idx >> 7, c = idx & 127;
        float v = vl[k * 129 + c] * f_rn[k];
        vl[k * 129 + c] = v;
        gtot += v * v;
    }
#pragma unroll
    for (int off = 16; off > 0; off >>= 1) gtot += __shfl_xor_sync(0xffffffffu, gtot, off);
    if (lane == 0) f_rb[w] = gtot;
    __syncthreads();
    if (tid == 0) {
        float t = 0.f;
#pragma unroll
        for (int q = 0; q < 8; ++q) t += f_rb[q];
        *f_gs = 1.f / fmaxf(sqrtf(t), 1e-12f);
    }
    __syncthreads();
    float gs = *f_gs;
#pragma unroll
    for (int it = 0; it < 32; ++it) {
        int idx = tid + it * 256;
        int k = idx >> 7, c = idx & 127;
        out[(size_t)n * (Kdim * Cdim) + idx] = vl[k * 129 + c] * gs;
    }
}

// =====================================================================
extern "C" void kernel_launch(void* const* d_in, const int* in_sizes, int n_in,
                              void* d_out, int out_size) {
    const float* x      = (const float*)d_in[0];
    const float* cent   = (const float*)d_in[2];
    const float* conv_w = (const float*)d_in[3];
    const float* conv_b = (const float*)d_in[4];
    float* out = (float*)d_out;

    cudaFuncSetAttribute(k_fused, cudaFuncAttributeMaxDynamicSharedMemorySize, L_SMEM);

    k_zero<<<512, 256>>>();
    k_fused<<<dim3(32, 64), 256, L_SMEM>>>(x, conv_w, conv_b, cent, out);
}

// round 16
// speedup vs baseline: 1.1029x; 1.1029x over previous
#include <cuda_runtime.h>
#include <cuda_bf16.h>
#include <cstdint>
#include <math.h>

#define Nn 64
#define Cdim 128
#define Pdim 4096
#define Kdim 64

// ---- device scratch ----
__device__ float g_asum_p[Nn * 32 * Kdim];             // 512 KB (per-tile asum partials)
__device__ float g_vpart[(size_t)Nn * Cdim * Kdim];    // 2 MB   [n][c][k] red-accumulated

// ---- mma / ldmatrix wrappers ----
__device__ __forceinline__ uint32_t smem_u32(const void* p) {
    uint32_t a;
    asm("{ .reg .u64 t; cvta.to.shared.u64 t, %1; cvt.u32.u64 %0, t; }" : "=r"(a) : "l"(p));
    return a;
}
__device__ __forceinline__ void ldsm_x4(uint32_t* r, uint32_t addr) {
    asm volatile("ldmatrix.sync.aligned.m8n8.x4.shared.b16 {%0,%1,%2,%3}, [%4];"
                 : "=r"(r[0]), "=r"(r[1]), "=r"(r[2]), "=r"(r[3]) : "r"(addr));
}
__device__ __forceinline__ void ldsm_x2_trans(uint32_t* r, uint32_t addr) {
    asm volatile("ldmatrix.sync.aligned.m8n8.x2.trans.shared.b16 {%0,%1}, [%2];"
                 : "=r"(r[0]), "=r"(r[1]) : "r"(addr));
}
__device__ __forceinline__ void mma_bf16(float* d, const uint32_t* a, const uint32_t* b) {
    asm volatile(
        "mma.sync.aligned.m16n8k16.row.col.f32.bf16.bf16.f32 "
        "{%0,%1,%2,%3}, {%4,%5,%6,%7}, {%8,%9}, {%0,%1,%2,%3};"
        : "+f"(d[0]), "+f"(d[1]), "+f"(d[2]), "+f"(d[3])
        : "r"(a[0]), "r"(a[1]), "r"(a[2]), "r"(a[3]), "r"(b[0]), "r"(b[1]));
}
__device__ __forceinline__ void split_bf16(float v, __nv_bfloat16& h, __nv_bfloat16& l) {
    h = __float2bfloat16(v);
    l = __float2bfloat16(v - __bfloat162float(h));
}
__device__ __forceinline__ uint32_t cvt2bf(float lo, float hi) {
    uint32_t r;
    asm("cvt.rn.bf16x2.f32 %0, %1, %2;" : "=r"(r) : "f"(hi), "f"(lo));
    return r;
}
__device__ __forceinline__ float bfp_lo(uint32_t pair) { return __uint_as_float(pair << 16); }
__device__ __forceinline__ float bfp_hi(uint32_t pair) { return __uint_as_float(pair & 0xFFFF0000u); }
#define REDG_ADD(addr, v) \
    asm volatile("red.global.add.f32 [%0], %1;" :: "l"(addr), "f"(v) : "memory")

// =====================================================================
// K_zero: zero the vlad accumulator (2 MB) each launch.
// Also warms the REDG target lines in L2 right before k_fused's atomics.
// =====================================================================
__global__ __launch_bounds__(256) void k_zero() {
    int i = blockIdx.x * 256 + threadIdx.x;
    ((float4*)g_vpart)[i] = make_float4(0.f, 0.f, 0.f, 0.f);
}

// =====================================================================
// K_fused: per (n, 128-pixel tile):
//   logits GEMM (3-term bf16 split, persistent x-hi plane) -> softmax ->
//   a' staged to smem -> vlad MMA partial [c=128][k=64] -> red to g_vpart[n].
// smem 91648 B, 2 CTAs/SM.
// =====================================================================
#define OFF_WH 0                    // 64*136*2 = 17408
#define OFF_WL 17408
#define OFF_XF 34816                // x hi full: 128*136*2 = 34816
#define OFF_XL 69632                // x lo double buffer: 2 * 32*136*2 = 17408 (a' later)
#define OFF_SP 87040                // s_part 1024 floats
#define OFF_SA 91136                // 64 floats
#define OFF_SB 91392                // 64 floats
#define L_SMEM 91648
#define XLPLANE 4352                // 32*136 elems per lo plane

__global__ __launch_bounds__(256, 2) void k_fused(const float* __restrict__ x,
                                                  const float* __restrict__ conv_w,
                                                  const float* __restrict__ conv_b) {
    extern __shared__ __align__(16) char dsm[];
    __nv_bfloat16* wh = (__nv_bfloat16*)(dsm + OFF_WH);
    __nv_bfloat16* wl = (__nv_bfloat16*)(dsm + OFF_WL);
    __nv_bfloat16* xf = (__nv_bfloat16*)(dsm + OFF_XF);   // persistent hi plane [128][136]
    __nv_bfloat16* xlb = (__nv_bfloat16*)(dsm + OFF_XL);  // lo double buffer
    __nv_bfloat16* a_s = (__nv_bfloat16*)(dsm + OFF_XL);  // a' staging (aliases dead lo bufs)
    float* s_part = (float*)(dsm + OFF_SP);
    float* s_asum = (float*)(dsm + OFF_SA);
    float* s_b = (float*)(dsm + OFF_SB);

    const int n = blockIdx.y;
    const int p0 = blockIdx.x * 128;
    const int tid = threadIdx.x;
    const int w = tid >> 5, lane = tid & 31;
    const int pw = w * 16;

    const uint32_t u_wh = smem_u32(wh), u_wl = smem_u32(wl);
    const uint32_t u_xf = smem_u32(xf);

    // stage W hi/lo (64x128, pitch 136)
#pragma unroll
    for (int r = 0; r < 8; ++r) {
        int f4 = tid + r * 256;
        int row = f4 >> 5, col4 = f4 & 31;
        float4 v = *(const float4*)(conv_w + row * 128 + col4 * 4);
        __nv_bfloat16 h, l;
        split_bf16(v.x, h, l); wh[row * 136 + col4 * 4 + 0] = h; wl[row * 136 + col4 * 4 + 0] = l;
        split_bf16(v.y, h, l); wh[row * 136 + col4 * 4 + 1] = h; wl[row * 136 + col4 * 4 + 1] = l;
        split_bf16(v.z, h, l); wh[row * 136 + col4 * 4 + 2] = h; wl[row * 136 + col4 * 4 + 2] = l;
        split_bf16(v.w, h, l); wh[row * 136 + col4 * 4 + 3] = h; wl[row * 136 + col4 * 4 + 3] = l;
    }
    if (tid < 64) { s_b[tid] = conv_b[tid]; s_asum[tid] = 0.f; }

    float acc[4][2][4];
#pragma unroll
    for (int a = 0; a < 4; ++a)
#pragma unroll
        for (int b = 0; b < 2; ++b)
#pragma unroll
            for (int c = 0; c < 4; ++c) acc[a][b][c] = 0.f;

    const float* xg = x + (size_t)n * Cdim * Pdim + p0;
    const int rbase = tid >> 5;          // 0..7
    const int col4 = tid & 31;           // pixel quad

    float ss0 = 0.f, ss1 = 0.f, ss2 = 0.f, ss3 = 0.f;
    float4 vx[4];

    // prologue: chunk 0 load + stage (hi -> xf rows 0..31, lo -> buffer 0)
#pragma unroll
    for (int r = 0; r < 4; ++r)
        vx[r] = *(const float4*)(xg + (size_t)(rbase + 8 * r) * Pdim + col4 * 4);
    {
        __nv_bfloat16* cxl = xlb;
#pragma unroll
        for (int r = 0; r < 4; ++r) {
            float4 v = vx[r];
            ss0 += v.x * v.x; ss1 += v.y * v.y; ss2 += v.z * v.z; ss3 += v.w * v.w;
            uint32_t h01 = cvt2bf(v.x, v.y), h23 = cvt2bf(v.z, v.w);
            float l0 = v.x - bfp_lo(h01), l1 = v.y - bfp_hi(h01);
            float l2 = v.z - bfp_lo(h23), l3 = v.w - bfp_hi(h23);
            int row = rbase + 8 * r;
            *(uint2*)&xf[row * 136 + col4 * 4] = make_uint2(h01, h23);
            *(uint2*)&cxl[row * 136 + col4 * 4] = make_uint2(cvt2bf(l0, l1), cvt2bf(l2, l3));
        }
    }
    __syncthreads();

#pragma unroll
    for (int cbi = 0; cbi < 4; ++cbi) {
        const int cb = cbi * 32;
        if (cbi < 3) {
#pragma unroll
            for (int r = 0; r < 4; ++r)
                vx[r] = *(const float4*)(xg + (size_t)(cb + 32 + rbase + 8 * r) * Pdim + col4 * 4);
        }

        const uint32_t u_xl = smem_u32(xlb + (cbi & 1) * XLPLANE);
#pragma unroll
        for (int ks = 0; ks < 2; ++ks) {
            uint32_t bh[2][2], bl[2][2];
#pragma unroll
            for (int nt = 0; nt < 2; ++nt) {
                uint32_t offh = (uint32_t)(((cb + ks * 16 + (lane & 15)) * 136 + pw + nt * 8) * 2);
                uint32_t offl = (uint32_t)(((ks * 16 + (lane & 15)) * 136 + pw + nt * 8) * 2);
                ldsm_x2_trans(bh[nt], u_xf + offh);
                ldsm_x2_trans(bl[nt], u_xl + offl);
            }
#pragma unroll
            for (int mt = 0; mt < 4; ++mt) {
                uint32_t ah[4], al[4];
                uint32_t off = (uint32_t)(((mt * 16 + (lane & 15)) * 136 + cb + ks * 16 + (lane >> 4) * 8) * 2);
                ldsm_x4(ah, u_wh + off);
                ldsm_x4(al, u_wl + off);
#pragma unroll
                for (int nt = 0; nt < 2; ++nt) {
                    mma_bf16(acc[mt][nt], ah, bh[nt]);
                    mma_bf16(acc[mt][nt], ah, bl[nt]);
                    mma_bf16(acc[mt][nt], al, bh[nt]);
                }
            }
        }

        if (cbi < 3) {
            __nv_bfloat16* cxl = xlb + ((cbi + 1) & 1) * XLPLANE;
#pragma unroll
            for (int r = 0; r < 4; ++r) {
                float4 v = vx[r];
                ss0 += v.x * v.x; ss1 += v.y * v.y; ss2 += v.z * v.z; ss3 += v.w * v.w;
                uint32_t h01 = cvt2bf(v.x, v.y), h23 = cvt2bf(v.z, v.w);
                float l0 = v.x - bfp_lo(h01), l1 = v.y - bfp_hi(h01);
                float l2 = v.z - bfp_lo(h23), l3 = v.w - bfp_hi(h23);
                int row = rbase + 8 * r;
                *(uint2*)&xf[(cb + 32 + row) * 136 + col4 * 4] = make_uint2(h01, h23);
                *(uint2*)&cxl[row * 136 + col4 * 4] = make_uint2(cvt2bf(l0, l1), cvt2bf(l2, l3));
            }
        }
        __syncthreads();
    }

    // sumsq reduce (in place)
    *(float4*)&s_part[rbase * 128 + col4 * 4] = make_float4(ss0, ss1, ss2, ss3);
    __syncthreads();
    float tot = 0.f;
    if (tid < 128) {
#pragma unroll
        for (int q = 0; q < 8; ++q) tot += s_part[q * 128 + tid];
    }
    __syncthreads();
    if (tid < 128) s_part[tid] = 1.f / fmaxf(sqrtf(tot), 1e-12f);
    __syncthreads();
    float* s_inv = s_part;

    float iv0[2], iv1[2];
#pragma unroll
    for (int nt = 0; nt < 2; ++nt) {
        int c0 = pw + nt * 8 + (lane & 3) * 2;
        iv0[nt] = s_inv[c0];
        iv1[nt] = s_inv[c0 + 1];
    }
    float bb0[4], bb1[4];
#pragma unroll
    for (int mt = 0; mt < 4; ++mt) {
        bb0[mt] = s_b[mt * 16 + (lane >> 2)];
        bb1[mt] = s_b[mt * 16 + (lane >> 2) + 8];
    }
    float l[4][2][4];
#pragma unroll
    for (int mt = 0; mt < 4; ++mt)
#pragma unroll
        for (int nt = 0; nt < 2; ++nt) {
            l[mt][nt][0] = acc[mt][nt][0] * iv0[nt] + bb0[mt];
            l[mt][nt][1] = acc[mt][nt][1] * iv1[nt] + bb0[mt];
            l[mt][nt][2] = acc[mt][nt][2] * iv0[nt] + bb1[mt];
            l[mt][nt][3] = acc[mt][nt][3] * iv1[nt] + bb1[mt];
        }
    float mx0[2], mx1[2];
#pragma unroll
    for (int nt = 0; nt < 2; ++nt) {
        float m0 = -1e30f, m1 = -1e30f;
#pragma unroll
        for (int mt = 0; mt < 4; ++mt) {
            m0 = fmaxf(m0, fmaxf(l[mt][nt][0], l[mt][nt][2]));
            m1 = fmaxf(m1, fmaxf(l[mt][nt][1], l[mt][nt][3]));
        }
#pragma unroll
        for (int s = 4; s < 32; s <<= 1) {
            m0 = fmaxf(m0, __shfl_xor_sync(0xffffffffu, m0, s));
            m1 = fmaxf(m1, __shfl_xor_sync(0xffffffffu, m1, s));
        }
        mx0[nt] = m0; mx1[nt] = m1;
    }
    float sm0[2], sm1[2];
#pragma unroll
    for (int nt = 0; nt < 2; ++nt) {
        float s0 = 0.f, s1 = 0.f;
#pragma unroll
        for (int mt = 0; mt < 4; ++mt) {
            l[mt][nt][0] = __expf(l[mt][nt][0] - mx0[nt]); s0 += l[mt][nt][0];
            l[mt][nt][2] = __expf(l[mt][nt][2] - mx0[nt]); s0 += l[mt][nt][2];
            l[mt][nt][1] = __expf(l[mt][nt][1] - mx1[nt]); s1 += l[mt][nt][1];
            l[mt][nt][3] = __expf(l[mt][nt][3] - mx1[nt]); s1 += l[mt][nt][3];
        }
#pragma unroll
        for (int s = 4; s < 32; s <<= 1) {
            s0 += __shfl_xor_sync(0xffffffffu, s0, s);
            s1 += __shfl_xor_sync(0xffffffffu, s1, s);
        }
        sm0[nt] = 1.f / s0; sm1[nt] = 1.f / s1;
    }
    // a' = a*inv -> stage to a_s [64 k rows][128 px], pitch 136; asum partials.
    float srow0[4] = {0, 0, 0, 0}, srow1[4] = {0, 0, 0, 0};
#pragma unroll
    for (int mt = 0; mt < 4; ++mt) {
        int r0 = mt * 16 + (lane >> 2);
#pragma unroll
        for (int nt = 0; nt < 2; ++nt) {
            int c0 = pw + nt * 8 + (lane & 3) * 2;
            float a0 = l[mt][nt][0] * sm0[nt];
            float a1 = l[mt][nt][1] * sm1[nt];
            float a2 = l[mt][nt][2] * sm0[nt];
            float a3 = l[mt][nt][3] * sm1[nt];
            srow0[mt] += a0 + a1;
            srow1[mt] += a2 + a3;
            *(uint32_t*)&a_s[r0 * 136 + c0] = cvt2bf(a0 * iv0[nt], a1 * iv1[nt]);
            *(uint32_t*)&a_s[(r0 + 8) * 136 + c0] = cvt2bf(a2 * iv0[nt], a3 * iv1[nt]);
        }
    }
#pragma unroll
    for (int mt = 0; mt < 4; ++mt) {
        float t0 = srow0[mt], t1 = srow1[mt];
        t0 += __shfl_xor_sync(0xffffffffu, t0, 1); t0 += __shfl_xor_sync(0xffffffffu, t0, 2);
        t1 += __shfl_xor_sync(0xffffffffu, t1, 1); t1 += __shfl_xor_sync(0xffffffffu, t1, 2);
        if ((lane & 3) == 0) {
            atomicAdd(&s_asum[mt * 16 + (lane >> 2)], t0);
            atomicAdd(&s_asum[mt * 16 + (lane >> 2) + 8], t1);
        }
    }
    __syncthreads();
    if (tid < 64) g_asum_p[(n * 32 + blockIdx.x) * Kdim + tid] = s_asum[tid];

    // ---- vlad MMA: D[c=128][k=64] partial = xf[c,p] * a_s[k,p], K=128 px ----
    const uint32_t u_as = smem_u32(a_s);
    float acc2[8][4];
#pragma unroll
    for (int a = 0; a < 8; ++a)
#pragma unroll
        for (int b = 0; b < 4; ++b) acc2[a][b] = 0.f;

#pragma unroll
    for (int ks = 0; ks < 8; ++ks) {
        uint32_t ah[4];
        uint32_t offA = (uint32_t)(((w * 16 + (lane & 15)) * 136 + ks * 16 + (lane >> 4) * 8) * 2);
        ldsm_x4(ah, u_xf + offA);
#pragma unroll
        for (int ntp = 0; ntp < 4; ++ntp) {
            uint32_t b4[4];
            int row = ntp * 16 + ((lane >> 4) << 3) + (lane & 7);
            int col = ks * 16 + ((lane >> 3) & 1) * 8;
            ldsm_x4(b4, u_as + (uint32_t)((row * 136 + col) * 2));
            mma_bf16(acc2[2 * ntp], ah, b4);
            mma_bf16(acc2[2 * ntp + 1], ah, b4 + 2);
        }
    }

    // red-accumulate partial into g_vpart[n][c][k]
    float* vp = g_vpart + (size_t)n * (Cdim * Kdim);
    int r0v = w * 16 + (lane >> 2);
    int c0v = (lane & 3) * 2;
#pragma unroll
    for (int nt = 0; nt < 8; ++nt) {
        float* d0 = vp + (size_t)r0v * Kdim + nt * 8 + c0v;
        float* d1 = vp + (size_t)(r0v + 8) * Kdim + nt * 8 + c0v;
        REDG_ADD(d0, acc2[nt][0]);
        REDG_ADD(d0 + 1, acc2[nt][1]);
        REDG_ADD(d1, acc2[nt][2]);
        REDG_ADD(d1 + 1, acc2[nt][3]);
    }
}

// =====================================================================
// K_final: 1024 threads. Single vlad partial + 32 asum partials.
// =====================================================================
__global__ __launch_bounds__(1024) void k_final(const float* __restrict__ cent,
                                                float* __restrict__ out) {
    const int n = blockIdx.x;
    const int tid = threadIdx.x;
    __shared__ float vl[Kdim * 129];
    __shared__ float rn[Kdim];
    __shared__ float redb[32];
    __shared__ float s_asum[64];
    __shared__ float gscale;

    if (tid < 64) {
        float s = 0.f;
#pragma unroll
        for (int t = 0; t < 32; ++t) s += g_asum_p[(n * 32 + t) * Kdim + tid];
        s_asum[tid] = s;
    }
    __syncthreads();

    const float* vp = g_vpart + (size_t)n * (Cdim * Kdim);
#pragma unroll
    for (int it = 0; it < 2; ++it) {
        int idx = (tid + it * 1024) * 4;
        float4 s = *(const float4*)(vp + idx);
        int c = idx >> 6, k = idx & 63;
        vl[(k + 0) * 129 + c] = s.x - s_asum[k + 0] * cent[(k + 0) * Cdim + c];
        vl[(k + 1) * 129 + c] = s.y - s_asum[k + 1] * cent[(k + 1) * Cdim + c];
        vl[(k + 2) * 129 + c] = s.z - s_asum[k + 2] * cent[(k + 2) * Cdim + c];
        vl[(k + 3) * 129 + c] = s.w - s_asum[k + 3] * cent[(k + 3) * Cdim + c];
    }
    __syncthreads();

    int w = tid >> 5, lane = tid & 31;
#pragma unroll
    for (int kk = 0; kk < 2; ++kk) {
        int k = w * 2 + kk;
        float t = 0.f;
#pragma unroll
        for (int m = 0; m < 4; ++m) {
            float v = vl[k * 129 + lane + m * 32];
            t += v * v;
        }
#pragma unroll
        for (int off = 16; off > 0; off >>= 1) t += __shfl_xor_sync(0xffffffffu, t, off);
        if (lane == 0) rn[k] = 1.f / fmaxf(sqrtf(t), 1e-12f);
    }
    __syncthreads();

    float tot = 0.f;
#pragma unroll
    for (int it = 0; it < 8; ++it) {
        int idx = tid + it * 1024;
        int k = idx >> 7, c = idx & 127;
        float v = vl[k * 129 + c] * rn[k];
        vl[k * 129 + c] = v;
        tot += v * v;
    }
#pragma unroll
    for (int off = 16; off > 0; off >>= 1) tot += __shfl_xor_sync(0xffffffffu, tot, off);
    if (lane == 0) redb[w] = tot;
    __syncthreads();
    if (tid == 0) {
        float t = 0.f;
#pragma unroll
        for (int q = 0; q < 32; ++q) t += redb[q];
        gscale = 1.f / fmaxf(sqrtf(t), 1e-12f);
    }
    __syncthreads();
    float gs = gscale;
#pragma unroll
    for (int it = 0; it < 8; ++it) {
        int idx = tid + it * 1024;
        int k = idx >> 7, c = idx & 127;
        out[(size_t)n * (Kdim * Cdim) + idx] = vl[k * 129 + c] * gs;
    }
}

// =====================================================================
extern "C" void kernel_launch(void* const* d_in, const int* in_sizes, int n_in,
                              void* d_out, int out_size) {
    const float* x      = (const float*)d_in[0];
    const float* cent   = (const float*)d_in[2];
    const float* conv_w = (const float*)d_in[3];
    const float* conv_b = (const float*)d_in[4];
    float* out = (float*)d_out;

    cudaFuncSetAttribute(k_fused, cudaFuncAttributeMaxDynamicSharedMemorySize, L_SMEM);

    k_zero<<<512, 256>>>();
    k_fused<<<dim3(32, 64), 256, L_SMEM>>>(x, conv_w, conv_b);
    k_final<<<64, 1024>>>(cent, out);
}

// round 17
// speedup vs baseline: 1.1102x; 1.0066x over previous
#include <cuda_runtime.h>
#include <cuda_bf16.h>
#include <cstdint>
#include <math.h>

#define Nn 64
#define Cdim 128
#define Pdim 4096
#define Kdim 64

// ---- device scratch ----
__device__ float g_asum_p[Nn * 32 * Kdim];             // 512 KB (per-tile asum partials)
__device__ float g_vpart[(size_t)Nn * Cdim * Kdim];    // 2 MB   [n][c][k] red-accumulated

// ---- mma / ldmatrix wrappers ----
__device__ __forceinline__ uint32_t smem_u32(const void* p) {
    uint32_t a;
    asm("{ .reg .u64 t; cvta.to.shared.u64 t, %1; cvt.u32.u64 %0, t; }" : "=r"(a) : "l"(p));
    return a;
}
__device__ __forceinline__ void ldsm_x4(uint32_t* r, uint32_t addr) {
    asm volatile("ldmatrix.sync.aligned.m8n8.x4.shared.b16 {%0,%1,%2,%3}, [%4];"
                 : "=r"(r[0]), "=r"(r[1]), "=r"(r[2]), "=r"(r[3]) : "r"(addr));
}
__device__ __forceinline__ void ldsm_x2_trans(uint32_t* r, uint32_t addr) {
    asm volatile("ldmatrix.sync.aligned.m8n8.x2.trans.shared.b16 {%0,%1}, [%2];"
                 : "=r"(r[0]), "=r"(r[1]) : "r"(addr));
}
__device__ __forceinline__ void mma_bf16(float* d, const uint32_t* a, const uint32_t* b) {
    asm volatile(
        "mma.sync.aligned.m16n8k16.row.col.f32.bf16.bf16.f32 "
        "{%0,%1,%2,%3}, {%4,%5,%6,%7}, {%8,%9}, {%0,%1,%2,%3};"
        : "+f"(d[0]), "+f"(d[1]), "+f"(d[2]), "+f"(d[3])
        : "r"(a[0]), "r"(a[1]), "r"(a[2]), "r"(a[3]), "r"(b[0]), "r"(b[1]));
}
__device__ __forceinline__ void split_bf16(float v, __nv_bfloat16& h, __nv_bfloat16& l) {
    h = __float2bfloat16(v);
    l = __float2bfloat16(v - __bfloat162float(h));
}
__device__ __forceinline__ uint32_t cvt2bf(float lo, float hi) {
    uint32_t r;
    asm("cvt.rn.bf16x2.f32 %0, %1, %2;" : "=r"(r) : "f"(hi), "f"(lo));
    return r;
}
__device__ __forceinline__ float bfp_lo(uint32_t pair) { return __uint_as_float(pair << 16); }
__device__ __forceinline__ float bfp_hi(uint32_t pair) { return __uint_as_float(pair & 0xFFFF0000u); }
#define REDG_ADD(addr, v) \
    asm volatile("red.global.add.f32 [%0], %1;" :: "l"(addr), "f"(v) : "memory")

// =====================================================================
// K_fused: per (n, 128-pixel tile):
//   logits GEMM (3-term bf16 split, persistent x-hi plane) -> softmax ->
//   a' staged to smem -> vlad MMA partial [c=128][k=64] -> red to g_vpart[n].
// smem 91648 B, 2 CTAs/SM.
// =====================================================================
#define OFF_WH 0                    // 64*136*2 = 17408
#define OFF_WL 17408
#define OFF_XF 34816                // x hi full: 128*136*2 = 34816
#define OFF_XL 69632                // x lo double buffer: 2 * 32*136*2 = 17408 (a' later)
#define OFF_SP 87040                // s_part 1024 floats
#define OFF_SA 91136                // 64 floats
#define OFF_SB 91392                // 64 floats
#define L_SMEM 91648
#define XLPLANE 4352                // 32*136 elems per lo plane

__global__ __launch_bounds__(256, 2) void k_fused(const float* __restrict__ x,
                                                  const float* __restrict__ conv_w,
                                                  const float* __restrict__ conv_b) {
    extern __shared__ __align__(16) char dsm[];
    __nv_bfloat16* wh = (__nv_bfloat16*)(dsm + OFF_WH);
    __nv_bfloat16* wl = (__nv_bfloat16*)(dsm + OFF_WL);
    __nv_bfloat16* xf = (__nv_bfloat16*)(dsm + OFF_XF);   // persistent hi plane [128][136]
    __nv_bfloat16* xlb = (__nv_bfloat16*)(dsm + OFF_XL);  // lo double buffer
    __nv_bfloat16* a_s = (__nv_bfloat16*)(dsm + OFF_XL);  // a' staging (aliases dead lo bufs)
    float* s_part = (float*)(dsm + OFF_SP);
    float* s_asum = (float*)(dsm + OFF_SA);
    float* s_b = (float*)(dsm + OFF_SB);

    const int n = blockIdx.y;
    const int p0 = blockIdx.x * 128;
    const int tid = threadIdx.x;
    const int w = tid >> 5, lane = tid & 31;
    const int pw = w * 16;

    const uint32_t u_wh = smem_u32(wh), u_wl = smem_u32(wl);
    const uint32_t u_xf = smem_u32(xf);

    // stage W hi/lo (64x128, pitch 136)
#pragma unroll
    for (int r = 0; r < 8; ++r) {
        int f4 = tid + r * 256;
        int row = f4 >> 5, col4 = f4 & 31;
        float4 v = *(const float4*)(conv_w + row * 128 + col4 * 4);
        __nv_bfloat16 h, l;
        split_bf16(v.x, h, l); wh[row * 136 + col4 * 4 + 0] = h; wl[row * 136 + col4 * 4 + 0] = l;
        split_bf16(v.y, h, l); wh[row * 136 + col4 * 4 + 1] = h; wl[row * 136 + col4 * 4 + 1] = l;
        split_bf16(v.z, h, l); wh[row * 136 + col4 * 4 + 2] = h; wl[row * 136 + col4 * 4 + 2] = l;
        split_bf16(v.w, h, l); wh[row * 136 + col4 * 4 + 3] = h; wl[row * 136 + col4 * 4 + 3] = l;
    }
    if (tid < 64) { s_b[tid] = conv_b[tid]; s_asum[tid] = 0.f; }

    float acc[4][2][4];
#pragma unroll
    for (int a = 0; a < 4; ++a)
#pragma unroll
        for (int b = 0; b < 2; ++b)
#pragma unroll
            for (int c = 0; c < 4; ++c) acc[a][b][c] = 0.f;

    const float* xg = x + (size_t)n * Cdim * Pdim + p0;
    const int rbase = tid >> 5;          // 0..7
    const int col4 = tid & 31;           // pixel quad

    float ss0 = 0.f, ss1 = 0.f, ss2 = 0.f, ss3 = 0.f;
    float4 vx[4];

    // prologue: chunk 0 load + stage (hi -> xf rows 0..31, lo -> buffer 0)
#pragma unroll
    for (int r = 0; r < 4; ++r)
        vx[r] = *(const float4*)(xg + (size_t)(rbase + 8 * r) * Pdim + col4 * 4);
    {
        __nv_bfloat16* cxl = xlb;
#pragma unroll
        for (int r = 0; r < 4; ++r) {
            float4 v = vx[r];
            ss0 += v.x * v.x; ss1 += v.y * v.y; ss2 += v.z * v.z; ss3 += v.w * v.w;
            uint32_t h01 = cvt2bf(v.x, v.y), h23 = cvt2bf(v.z, v.w);
            float l0 = v.x - bfp_lo(h01), l1 = v.y - bfp_hi(h01);
            float l2 = v.z - bfp_lo(h23), l3 = v.w - bfp_hi(h23);
            int row = rbase + 8 * r;
            *(uint2*)&xf[row * 136 + col4 * 4] = make_uint2(h01, h23);
            *(uint2*)&cxl[row * 136 + col4 * 4] = make_uint2(cvt2bf(l0, l1), cvt2bf(l2, l3));
        }
    }
    __syncthreads();

#pragma unroll
    for (int cbi = 0; cbi < 4; ++cbi) {
        const int cb = cbi * 32;
        if (cbi < 3) {
#pragma unroll
            for (int r = 0; r < 4; ++r)
                vx[r] = *(const float4*)(xg + (size_t)(cb + 32 + rbase + 8 * r) * Pdim + col4 * 4);
        }

        const uint32_t u_xl = smem_u32(xlb + (cbi & 1) * XLPLANE);
#pragma unroll
        for (int ks = 0; ks < 2; ++ks) {
            uint32_t bh[2][2], bl[2][2];
#pragma unroll
            for (int nt = 0; nt < 2; ++nt) {
                uint32_t offh = (uint32_t)(((cb + ks * 16 + (lane & 15)) * 136 + pw + nt * 8) * 2);
                uint32_t offl = (uint32_t)(((ks * 16 + (lane & 15)) * 136 + pw + nt * 8) * 2);
                ldsm_x2_trans(bh[nt], u_xf + offh);
                ldsm_x2_trans(bl[nt], u_xl + offl);
            }
#pragma unroll
            for (int mt = 0; mt < 4; ++mt) {
                uint32_t ah[4], al[4];
                uint32_t off = (uint32_t)(((mt * 16 + (lane & 15)) * 136 + cb + ks * 16 + (lane >> 4) * 8) * 2);
                ldsm_x4(ah, u_wh + off);
                ldsm_x4(al, u_wl + off);
#pragma unroll
                for (int nt = 0; nt < 2; ++nt) {
                    mma_bf16(acc[mt][nt], ah, bh[nt]);
                    mma_bf16(acc[mt][nt], ah, bl[nt]);
                    mma_bf16(acc[mt][nt], al, bh[nt]);
                }
            }
        }

        if (cbi < 3) {
            __nv_bfloat16* cxl = xlb + ((cbi + 1) & 1) * XLPLANE;
#pragma unroll
            for (int r = 0; r < 4; ++r) {
                float4 v = vx[r];
                ss0 += v.x * v.x; ss1 += v.y * v.y; ss2 += v.z * v.z; ss3 += v.w * v.w;
                uint32_t h01 = cvt2bf(v.x, v.y), h23 = cvt2bf(v.z, v.w);
                float l0 = v.x - bfp_lo(h01), l1 = v.y - bfp_hi(h01);
                float l2 = v.z - bfp_lo(h23), l3 = v.w - bfp_hi(h23);
                int row = rbase + 8 * r;
                *(uint2*)&xf[(cb + 32 + row) * 136 + col4 * 4] = make_uint2(h01, h23);
                *(uint2*)&cxl[row * 136 + col4 * 4] = make_uint2(cvt2bf(l0, l1), cvt2bf(l2, l3));
            }
        }
        __syncthreads();
    }

    // sumsq reduce (in place)
    *(float4*)&s_part[rbase * 128 + col4 * 4] = make_float4(ss0, ss1, ss2, ss3);
    __syncthreads();
    float tot = 0.f;
    if (tid < 128) {
#pragma unroll
        for (int q = 0; q < 8; ++q) tot += s_part[q * 128 + tid];
    }
    __syncthreads();
    if (tid < 128) s_part[tid] = 1.f / fmaxf(sqrtf(tot), 1e-12f);
    __syncthreads();
    float* s_inv = s_part;

    float iv0[2], iv1[2];
#pragma unroll
    for (int nt = 0; nt < 2; ++nt) {
        int c0 = pw + nt * 8 + (lane & 3) * 2;
        iv0[nt] = s_inv[c0];
        iv1[nt] = s_inv[c0 + 1];
    }
    float bb0[4], bb1[4];
#pragma unroll
    for (int mt = 0; mt < 4; ++mt) {
        bb0[mt] = s_b[mt * 16 + (lane >> 2)];
        bb1[mt] = s_b[mt * 16 + (lane >> 2) + 8];
    }
    float l[4][2][4];
#pragma unroll
    for (int mt = 0; mt < 4; ++mt)
#pragma unroll
        for (int nt = 0; nt < 2; ++nt) {
            l[mt][nt][0] = acc[mt][nt][0] * iv0[nt] + bb0[mt];
            l[mt][nt][1] = acc[mt][nt][1] * iv1[nt] + bb0[mt];
            l[mt][nt][2] = acc[mt][nt][2] * iv0[nt] + bb1[mt];
            l[mt][nt][3] = acc[mt][nt][3] * iv1[nt] + bb1[mt];
        }
    float mx0[2], mx1[2];
#pragma unroll
    for (int nt = 0; nt < 2; ++nt) {
        float m0 = -1e30f, m1 = -1e30f;
#pragma unroll
        for (int mt = 0; mt < 4; ++mt) {
            m0 = fmaxf(m0, fmaxf(l[mt][nt][0], l[mt][nt][2]));
            m1 = fmaxf(m1, fmaxf(l[mt][nt][1], l[mt][nt][3]));
        }
#pragma unroll
        for (int s = 4; s < 32; s <<= 1) {
            m0 = fmaxf(m0, __shfl_xor_sync(0xffffffffu, m0, s));
            m1 = fmaxf(m1, __shfl_xor_sync(0xffffffffu, m1, s));
        }
        mx0[nt] = m0; mx1[nt] = m1;
    }
    float sm0[2], sm1[2];
#pragma unroll
    for (int nt = 0; nt < 2; ++nt) {
        float s0 = 0.f, s1 = 0.f;
#pragma unroll
        for (int mt = 0; mt < 4; ++mt) {
            l[mt][nt][0] = __expf(l[mt][nt][0] - mx0[nt]); s0 += l[mt][nt][0];
            l[mt][nt][2] = __expf(l[mt][nt][2] - mx0[nt]); s0 += l[mt][nt][2];
            l[mt][nt][1] = __expf(l[mt][nt][1] - mx1[nt]); s1 += l[mt][nt][1];
            l[mt][nt][3] = __expf(l[mt][nt][3] - mx1[nt]); s1 += l[mt][nt][3];
        }
#pragma unroll
        for (int s = 4; s < 32; s <<= 1) {
            s0 += __shfl_xor_sync(0xffffffffu, s0, s);
            s1 += __shfl_xor_sync(0xffffffffu, s1, s);
        }
        sm0[nt] = 1.f / s0; sm1[nt] = 1.f / s1;
    }
    // a' = a*inv -> stage to a_s [64 k rows][128 px], pitch 136; asum partials.
    float srow0[4] = {0, 0, 0, 0}, srow1[4] = {0, 0, 0, 0};
#pragma unroll
    for (int mt = 0; mt < 4; ++mt) {
        int r0 = mt * 16 + (lane >> 2);
#pragma unroll
        for (int nt = 0; nt < 2; ++nt) {
            int c0 = pw + nt * 8 + (lane & 3) * 2;
            float a0 = l[mt][nt][0] * sm0[nt];
            float a1 = l[mt][nt][1] * sm1[nt];
            float a2 = l[mt][nt][2] * sm0[nt];
            float a3 = l[mt][nt][3] * sm1[nt];
            srow0[mt] += a0 + a1;
            srow1[mt] += a2 + a3;
            *(uint32_t*)&a_s[r0 * 136 + c0] = cvt2bf(a0 * iv0[nt], a1 * iv1[nt]);
            *(uint32_t*)&a_s[(r0 + 8) * 136 + c0] = cvt2bf(a2 * iv0[nt], a3 * iv1[nt]);
        }
    }
#pragma unroll
    for (int mt = 0; mt < 4; ++mt) {
        float t0 = srow0[mt], t1 = srow1[mt];
        t0 += __shfl_xor_sync(0xffffffffu, t0, 1); t0 += __shfl_xor_sync(0xffffffffu, t0, 2);
        t1 += __shfl_xor_sync(0xffffffffu, t1, 1); t1 += __shfl_xor_sync(0xffffffffu, t1, 2);
        if ((lane & 3) == 0) {
            atomicAdd(&s_asum[mt * 16 + (lane >> 2)], t0);
            atomicAdd(&s_asum[mt * 16 + (lane >> 2) + 8], t1);
        }
    }
    __syncthreads();
    if (tid < 64) g_asum_p[(n * 32 + blockIdx.x) * Kdim + tid] = s_asum[tid];

    // ---- vlad MMA: D[c=128][k=64] partial = xf[c,p] * a_s[k,p], K=128 px ----
    const uint32_t u_as = smem_u32(a_s);
    float acc2[8][4];
#pragma unroll
    for (int a = 0; a < 8; ++a)
#pragma unroll
        for (int b = 0; b < 4; ++b) acc2[a][b] = 0.f;

#pragma unroll
    for (int ks = 0; ks < 8; ++ks) {
        uint32_t ah[4];
        uint32_t offA = (uint32_t)(((w * 16 + (lane & 15)) * 136 + ks * 16 + (lane >> 4) * 8) * 2);
        ldsm_x4(ah, u_xf + offA);
#pragma unroll
        for (int ntp = 0; ntp < 4; ++ntp) {
            uint32_t b4[4];
            int row = ntp * 16 + ((lane >> 4) << 3) + (lane & 7);
            int col = ks * 16 + ((lane >> 3) & 1) * 8;
            ldsm_x4(b4, u_as + (uint32_t)((row * 136 + col) * 2));
            mma_bf16(acc2[2 * ntp], ah, b4);
            mma_bf16(acc2[2 * ntp + 1], ah, b4 + 2);
        }
    }

    // red-accumulate partial into g_vpart[n][c][k]
    float* vp = g_vpart + (size_t)n * (Cdim * Kdim);
    int r0v = w * 16 + (lane >> 2);
    int c0v = (lane & 3) * 2;
#pragma unroll
    for (int nt = 0; nt < 8; ++nt) {
        float* d0 = vp + (size_t)r0v * Kdim + nt * 8 + c0v;
        float* d1 = vp + (size_t)(r0v + 8) * Kdim + nt * 8 + c0v;
        REDG_ADD(d0, acc2[nt][0]);
        REDG_ADD(d0 + 1, acc2[nt][1]);
        REDG_ADD(d1, acc2[nt][2]);
        REDG_ADD(d1 + 1, acc2[nt][3]);
    }
}

// =====================================================================
// K_final: 1024 threads. Single vlad partial + 32 asum partials.
// =====================================================================
__global__ __launch_bounds__(1024) void k_final(const float* __restrict__ cent,
                                                float* __restrict__ out) {
    const int n = blockIdx.x;
    const int tid = threadIdx.x;
    __shared__ float vl[Kdim * 129];
    __shared__ float rn[Kdim];
    __shared__ float redb[32];
    __shared__ float s_asum[64];
    __shared__ float gscale;

    if (tid < 64) {
        float s = 0.f;
#pragma unroll
        for (int t = 0; t < 32; ++t) s += g_asum_p[(n * 32 + t) * Kdim + tid];
        s_asum[tid] = s;
    }
    __syncthreads();

    const float* vp = g_vpart + (size_t)n * (Cdim * Kdim);
#pragma unroll
    for (int it = 0; it < 2; ++it) {
        int idx = (tid + it * 1024) * 4;
        float4 s = *(const float4*)(vp + idx);
        int c = idx >> 6, k = idx & 63;
        vl[(k + 0) * 129 + c] = s.x - s_asum[k + 0] * cent[(k + 0) * Cdim + c];
        vl[(k + 1) * 129 + c] = s.y - s_asum[k + 1] * cent[(k + 1) * Cdim + c];
        vl[(k + 2) * 129 + c] = s.z - s_asum[k + 2] * cent[(k + 2) * Cdim + c];
        vl[(k + 3) * 129 + c] = s.w - s_asum[k + 3] * cent[(k + 3) * Cdim + c];
    }
    __syncthreads();

    int w = tid >> 5, lane = tid & 31;
#pragma unroll
    for (int kk = 0; kk < 2; ++kk) {
        int k = w * 2 + kk;
        float t = 0.f;
#pragma unroll
        for (int m = 0; m < 4; ++m) {
            float v = vl[k * 129 + lane + m * 32];
            t += v * v;
        }
#pragma unroll
        for (int off = 16; off > 0; off >>= 1) t += __shfl_xor_sync(0xffffffffu, t, off);
        if (lane == 0) rn[k] = 1.f / fmaxf(sqrtf(t), 1e-12f);
    }
    __syncthreads();

    float tot = 0.f;
#pragma unroll
    for (int it = 0; it < 8; ++it) {
        int idx = tid + it * 1024;
        int k = idx >> 7, c = idx & 127;
        float v = vl[k * 129 + c] * rn[k];
        vl[k * 129 + c] = v;
        tot += v * v;
    }
#pragma unroll
    for (int off = 16; off > 0; off >>= 1) tot += __shfl_xor_sync(0xffffffffu, tot, off);
    if (lane == 0) redb[w] = tot;
    __syncthreads();
    if (tid == 0) {
        float t = 0.f;
#pragma unroll
        for (int q = 0; q < 32; ++q) t += redb[q];
        gscale = 1.f / fmaxf(sqrtf(t), 1e-12f);
    }
    __syncthreads();
    float gs = gscale;
#pragma unroll
    for (int it = 0; it < 8; ++it) {
        int idx = tid + it * 1024;
        int k = idx >> 7, c = idx & 127;
        out[(size_t)n * (Kdim * Cdim) + idx] = vl[k * 129 + c] * gs;
    }
}

// =====================================================================
extern "C" void kernel_launch(void* const* d_in, const int* in_sizes, int n_in,
                              void* d_out, int out_size) {
    const float* x      = (const float*)d_in[0];
    const float* cent   = (const float*)d_in[2];
    const float* conv_w = (const float*)d_in[3];
    const float* conv_b = (const float*)d_in[4];
    float* out = (float*)d_out;

    cudaFuncSetAttribute(k_fused, cudaFuncAttributeMaxDynamicSharedMemorySize, L_SMEM);

    // zero the vlad accumulator via a graph memset node (cheaper than a kernel)
    void* vp_addr = nullptr;
    cudaGetSymbolAddress(&vp_addr, g_vpart);
    cudaMemsetAsync(vp_addr, 0, sizeof(float) * (size_t)Nn * Cdim * Kdim);

    k_fused<<<dim3(32, 64), 256, L_SMEM>>>(x, conv_w, conv_b);
    k_final<<<64, 1024>>>(cent, out);
}